// round 13
// baseline (speedup 1.0000x reference)
#include <cuda_runtime.h>
#include <math.h>

#define SEQ 40
#define HID 128
#define TPB 896               // 28 warps, 1 CTA/SM (reg ceiling 72)
#define NCTA 148              // one persistent CTA per SM
#define TROWS 264             // 256 pair-combo rows + 8 w_in channel rows

// Pair-combination table, lane-permuted (dest neuron h = 32*kk + l lives at
// element 4*l + kk of each 128-float row):
//  row (k*64 + 4*i + c), c in 1..3: combo row for source pair
//      a = 32k + 2i, b = 32k + 2i + 1:   (c&1)*w_rec[:,a] + ((c>>1)&1)*w_rec[:,b]
//  row 256+ch: w_in channel ch column
__device__ float g_tbl[TROWS * HID];
__device__ int g_ctr;

__global__ void prep_kernel(const float* __restrict__ w_rec,
                            const float* __restrict__ w_in) {
    int tid = blockIdx.x * blockDim.x + threadIdx.x;
    if (tid == 0) g_ctr = 0;
    if (tid < 256 * HID) {
        int row = tid >> 7;          // 0..255
        int e   = tid & 127;         // element = 4*l + kk
        int l   = e >> 2;
        int kk  = e & 3;
        int h   = 32 * kk + l;       // dest neuron
        int k   = row >> 6;          // source ballot word
        int i   = (row >> 2) & 15;   // pair index
        int c   = row & 3;           // combo
        int a = 32 * k + 2 * i;
        int b = a + 1;
        float va = (c & 1) ? w_rec[h * HID + a] : 0.0f;
        float vb = (c & 2) ? w_rec[h * HID + b] : 0.0f;
        g_tbl[row * HID + e] = va + vb;
    } else if (tid < 256 * HID + 8 * HID) {
        int r  = tid - 256 * HID;
        int ch = r >> 7;
        int e  = r & 127;
        int l  = e >> 2;
        int kk = e & 3;
        int h  = 32 * kk + l;
        g_tbl[(256 + ch) * HID + e] = w_in[h * 8 + ch];
    }
}

// ---- packed f32x2 helpers (sm_103a) ----
__device__ __forceinline__ unsigned long long pk2(float a, float b) {
    unsigned long long r;
    asm("mov.b64 %0, {%1, %2};" : "=l"(r) : "f"(a), "f"(b));
    return r;
}
__device__ __forceinline__ void upk2(unsigned long long v, float& a, float& b) {
    asm("mov.b64 {%0, %1}, %2;" : "=f"(a), "=f"(b) : "l"(v));
}
__device__ __forceinline__ unsigned long long addx2(unsigned long long a,
                                                    unsigned long long b) {
    unsigned long long r;
    asm("add.rn.f32x2 %0, %1, %2;" : "=l"(r) : "l"(a), "l"(b));
    return r;
}

__global__ __launch_bounds__(TPB, 1) void snn_kernel(
    const float* __restrict__ x,       // (B, 4)
    const float* __restrict__ w_out,   // (2, 128)
    const float* __restrict__ mask,    // (40, B, 128)
    float* __restrict__ out,           // (B, 2)
    int B)
{
    extern __shared__ ulonglong2 srec[];   // [TROWS][32 lanes] 16B = 132 KB

    {   // stage the pair table once per SM: coalesced, conflict-free
        const ulonglong2* src = reinterpret_cast<const ulonglong2*>(g_tbl);
        for (int i = threadIdx.x; i < TROWS * 32; i += TPB)
            srec[i] = src[i];
    }
    __syncthreads();

    const int lane = threadIdx.x & 31;
    const size_t mstride = (size_t)B * HID;

    // lane-dependent readout weights: hoisted out of the work loop
    float wo0[4], wo1[4];
    #pragma unroll
    for (int k = 0; k < 4; k++) {
        int h = 32 * k + lane;
        wo0[k] = w_out[h];
        wo1[k] = w_out[HID + h];
    }

    for (;;) {
        // ---- per-warp work stealing: one batch element per grab ----
        int b;
        if (lane == 0) b = atomicAdd(&g_ctr, 1);
        b = __shfl_sync(0xffffffffu, b, 0);
        if (b >= B) break;

        // ---- encoder constants (warp-uniform) ----
        float c_in[4], venc[4];
        int rowe[4];     // srec element index of this feature's w_in row
        #pragma unroll
        for (int f = 0; f < 4; f++) {
            float xv = x[(size_t)b * 4 + f];
            int ch = (xv > 0.0f) ? f : (f + 4);
            rowe[f] = (256 + ch) * 32;
            c_in[f] = 50.0f * fabsf(xv);
            venc[f] = 0.0f;
        }

        // ---- state: lane owns hidden neurons h = 32k + lane ----
        float v[4]   = {0.f, 0.f, 0.f, 0.f};
        float cur[4] = {0.f, 0.f, 0.f, 0.f};
        float vo0 = 0.f, io0 = 0.f, vo1 = 0.f, io1 = 0.f;
        float m0 = -1e30f, m1 = -1e30f;
        unsigned zb[4] = {0u, 0u, 0u, 0u};

        const float* mrow = mask + (size_t)b * HID + lane;
        float pm[4];
        #pragma unroll
        for (int k = 0; k < 4; k++) pm[k] = __ldcs(mrow + 32 * k);

        #pragma unroll 2
        for (int t = 0; t < SEQ; t++) {
            // ---- prefetch next step's mask row ----
            const float* nrow = (t < SEQ - 1) ? (mrow + mstride) : mrow;
            float pn[4];
            #pragma unroll
            for (int k = 0; k < 4; k++) pn[k] = __ldcs(nrow + 32 * k);

            // ---- encoder LIF step (warp-uniform spikes) ----
            bool es[4];
            #pragma unroll
            for (int f = 0; f < 4; f++) {
                float vd = fmaf(0.1f, c_in[f] - venc[f], venc[f]);
                es[f] = vd > 1.0f;
                venc[f] = es[f] ? 0.0f : vd;
            }

            // ---- recurrent LIF membrane update ----
            bool zn[4];
            #pragma unroll
            for (int k = 0; k < 4; k++) {
                float vd = fmaf(0.1f, cur[k] - v[k], v[k]);
                zn[k] = vd > 1.0f;
                v[k] = zn[k] ? 0.0f : vd;
                cur[k] *= 0.8f;
            }

            // ---- sparse current accumulation, dual packed accumulators ----
            unsigned long long c01  = pk2(cur[0], cur[1]);
            unsigned long long c23  = pk2(cur[2], cur[3]);
            unsigned long long c01b = 0ull;   // packed {0.f, 0.f}
            unsigned long long c23b = 0ull;

            // input channel rows (warp-uniform predicates)
            #pragma unroll
            for (int f = 0; f < 4; f++) {
                if (es[f]) {
                    ulonglong2 w = srec[rowe[f] + lane];
                    c01 = addx2(c01, w.x);
                    c23 = addx2(c23, w.y);
                }
            }
            // recurrent rows over z_prev, PAIR-compressed: scan active pairs
            // (bit 2i | bit 2i+1) and load ONE combo row per pair. Both-spike
            // pairs cost a single LDS.128. pp warp-uniform -> non-divergent.
            // Unroll-by-2 keeps two loads in flight.
            #pragma unroll
            for (int k = 0; k < 4; k++) {
                unsigned bits = zb[k];
                unsigned pp = (bits | (bits >> 1)) & 0x55555555u;
                const ulonglong2* basep = srec + (k * 64) * 32 + lane;
                while (pp) {
                    int p1 = __ffs(pp) - 1; pp &= pp - 1;      // p1 = 2*i
                    unsigned cb1 = (bits >> p1) & 3u;
                    ulonglong2 w1 = basep[(p1 * 2 + cb1) * 32]; // row k*64+4i+c
                    if (pp) {
                        int p2 = __ffs(pp) - 1; pp &= pp - 1;
                        unsigned cb2 = (bits >> p2) & 3u;
                        ulonglong2 w2 = basep[(p2 * 2 + cb2) * 32];
                        c01b = addx2(c01b, w2.x);
                        c23b = addx2(c23b, w2.y);
                    }
                    c01 = addx2(c01, w1.x);
                    c23 = addx2(c23, w1.y);
                }
            }
            c01 = addx2(c01, c01b);
            c23 = addx2(c23, c23b);
            upk2(c01, cur[0], cur[1]);
            upk2(c23, cur[2], cur[3]);

            // ---- publish new spikes ----
            #pragma unroll
            for (int k = 0; k < 4; k++)
                zb[k] = __ballot_sync(0xffffffffu, zn[k]);

            // ---- readout drive: (z_new * mask) @ w_out.T ----
            float d0 = 0.f, d1 = 0.f;
            #pragma unroll
            for (int k = 0; k < 4; k++) {
                float mv = zn[k] ? pm[k] : 0.0f;
                d0 = fmaf(mv, wo0[k], d0);
                d1 = fmaf(mv, wo1[k], d1);
            }
            unsigned long long d01 = pk2(d0, d1);
            #pragma unroll
            for (int off = 16; off; off >>= 1)
                d01 = addx2(d01, __shfl_xor_sync(0xffffffffu, d01, off));
            upk2(d01, d0, d1);

            // ---- LI readout (vo uses OLD io, matching reference) ----
            vo0 = fmaf(0.1f, io0 - vo0, vo0);
            vo1 = fmaf(0.1f, io1 - vo1, vo1);
            io0 = fmaf(0.8f, io0, d0);
            io1 = fmaf(0.8f, io1, d1);
            m0 = fmaxf(m0, vo0);
            m1 = fmaxf(m1, vo1);

            #pragma unroll
            for (int k = 0; k < 4; k++) pm[k] = pn[k];
            mrow = nrow;
        }

        if (lane == 0) {
            float mm = fmaxf(m0, m1);
            float e0 = expf(m0 - mm);
            float e1 = expf(m1 - mm);
            float inv = 1.0f / (e0 + e1);
            out[(size_t)b * 2 + 0] = e0 * inv;
            out[(size_t)b * 2 + 1] = e1 * inv;
        }
    }
}

extern "C" void kernel_launch(void* const* d_in, const int* in_sizes, int n_in,
                              void* d_out, int out_size) {
    const float* x     = (const float*)d_in[0];  // (B, 4)
    const float* w_in  = (const float*)d_in[1];  // (128, 8)
    const float* w_rec = (const float*)d_in[2];  // (128, 128)
    const float* w_out = (const float*)d_in[3];  // (2, 128)
    const float* mask  = (const float*)d_in[4];  // (40, B, 128)
    float* out = (float*)d_out;

    const int B = in_sizes[0] / 4;

    cudaFuncSetAttribute(snn_kernel,
                         cudaFuncAttributeMaxDynamicSharedMemorySize,
                         TROWS * HID * (int)sizeof(float));

    prep_kernel<<<(TROWS * HID + 255) / 256, 256>>>(w_rec, w_in);

    snn_kernel<<<NCTA, TPB, TROWS * HID * sizeof(float)>>>(
        x, w_out, mask, out, B);
}

// round 14
// speedup vs baseline: 1.0094x; 1.0094x over previous
#include <cuda_runtime.h>
#include <math.h>

#define SEQ 40
#define HID 128
#define WARPS 14
#define TPB (WARPS * 32)      // 448 x 2 CTAs -> 28 warps/SM, reg cap 72
#define NCTA 296              // 148 SMs x 2 CTAs
#define ROWS (HID + 64 + 8)   // 128 singles + 64 both-pair rows + 8 w_in rows

// Lane-permuted weight tile (R4 layout + both-pair block):
//  row j (<128):        g_wT[j*128 + 4*l + k] = w_rec[(32k+l)*128 + j]
//  row 128+16k+i:       both-pair row = w_rec[:,32k+2i] + w_rec[:,32k+2i+1]
//  row 192+ch:          w_in channel ch
__device__ float g_wT[ROWS * HID];
__device__ int g_ctr;

__global__ void prep_kernel(const float* __restrict__ w_rec,
                            const float* __restrict__ w_in) {
    int tid = blockIdx.x * blockDim.x + threadIdx.x;
    if (tid == 0) g_ctr = 0;
    if (tid < HID * HID) {
        int h = tid >> 7, j = tid & 127;
        g_wT[j * HID + ((h & 31) << 2) + (h >> 5)] = w_rec[tid];
    } else if (tid < HID * HID + 64 * HID) {
        int r = tid - HID * HID;
        int pr = r >> 7;            // 0..63 : pair index 16k+i
        int h  = r & 127;           // dest neuron
        int a  = 32 * (pr >> 4) + 2 * (pr & 15);
        g_wT[(HID + pr) * HID + ((h & 31) << 2) + (h >> 5)] =
            w_rec[h * HID + a] + w_rec[h * HID + a + 1];
    } else if (tid < HID * HID + 64 * HID + 8 * HID) {
        int r = tid - HID * HID - 64 * HID;
        int h = r >> 3, ch = r & 7;
        g_wT[(HID + 64 + ch) * HID + ((h & 31) << 2) + (h >> 5)] = w_in[r];
    }
}

// ---- packed f32x2 helpers (sm_103a) ----
__device__ __forceinline__ unsigned long long pk2(float a, float b) {
    unsigned long long r;
    asm("mov.b64 %0, {%1, %2};" : "=l"(r) : "f"(a), "f"(b));
    return r;
}
__device__ __forceinline__ void upk2(unsigned long long v, float& a, float& b) {
    asm("mov.b64 {%0, %1}, %2;" : "=f"(a), "=f"(b) : "l"(v));
}
__device__ __forceinline__ unsigned long long addx2(unsigned long long a,
                                                    unsigned long long b) {
    unsigned long long r;
    asm("add.rn.f32x2 %0, %1, %2;" : "=l"(r) : "l"(a), "l"(b));
    return r;
}

__global__ __launch_bounds__(TPB, 2) void snn_kernel(
    const float* __restrict__ x,       // (B, 4)
    const float* __restrict__ w_out,   // (2, 128)
    const float* __restrict__ mask,    // (40, B, 128)
    float* __restrict__ out,           // (B, 2)
    int B)
{
    extern __shared__ ulonglong2 srec[];   // [ROWS][32 lanes] 16B = 100 KB

    {   // stage weights once per (persistent) CTA: coalesced, conflict-free
        const ulonglong2* src = reinterpret_cast<const ulonglong2*>(g_wT);
        for (int i = threadIdx.x; i < ROWS * 32; i += TPB)
            srec[i] = src[i];
    }
    __syncthreads();

    const int lane = threadIdx.x & 31;
    const size_t mstride = (size_t)B * HID;

    // lane-dependent readout weights: hoisted out of the work loop
    float wo0[4], wo1[4];
    #pragma unroll
    for (int k = 0; k < 4; k++) {
        int h = 32 * k + lane;
        wo0[k] = w_out[h];
        wo1[k] = w_out[HID + h];
    }

    for (;;) {
        // ---- per-warp work stealing: one batch element per grab ----
        int b;
        if (lane == 0) b = atomicAdd(&g_ctr, 1);
        b = __shfl_sync(0xffffffffu, b, 0);
        if (b >= B) break;

        // ---- encoder constants (warp-uniform) ----
        float c_in[4], venc[4];
        int rowe[4];     // srec element index of this feature's w_in row
        #pragma unroll
        for (int f = 0; f < 4; f++) {
            float xv = x[(size_t)b * 4 + f];
            int ch = (xv > 0.0f) ? f : (f + 4);
            rowe[f] = (HID + 64 + ch) * 32;
            c_in[f] = 50.0f * fabsf(xv);
            venc[f] = 0.0f;
        }

        // ---- state: lane owns hidden neurons h = 32k + lane ----
        float v[4]   = {0.f, 0.f, 0.f, 0.f};
        float cur[4] = {0.f, 0.f, 0.f, 0.f};
        float vo0 = 0.f, io0 = 0.f, vo1 = 0.f, io1 = 0.f;
        float m0 = -1e30f, m1 = -1e30f;
        unsigned zb[4] = {0u, 0u, 0u, 0u};

        const float* mrow = mask + (size_t)b * HID + lane;
        float pm[4];
        #pragma unroll
        for (int k = 0; k < 4; k++) pm[k] = __ldcs(mrow + 32 * k);

        #pragma unroll 2
        for (int t = 0; t < SEQ; t++) {
            // ---- prefetch next step's mask row ----
            const float* nrow = (t < SEQ - 1) ? (mrow + mstride) : mrow;
            float pn[4];
            #pragma unroll
            for (int k = 0; k < 4; k++) pn[k] = __ldcs(nrow + 32 * k);

            // ---- encoder LIF step (warp-uniform spikes) ----
            bool es[4];
            #pragma unroll
            for (int f = 0; f < 4; f++) {
                float vd = fmaf(0.1f, c_in[f] - venc[f], venc[f]);
                es[f] = vd > 1.0f;
                venc[f] = es[f] ? 0.0f : vd;
            }

            // ---- recurrent LIF membrane update ----
            bool zn[4];
            #pragma unroll
            for (int k = 0; k < 4; k++) {
                float vd = fmaf(0.1f, cur[k] - v[k], v[k]);
                zn[k] = vd > 1.0f;
                v[k] = zn[k] ? 0.0f : vd;
                cur[k] *= 0.8f;
            }

            // ---- sparse current accumulation, dual packed accumulators ----
            unsigned long long c01  = pk2(cur[0], cur[1]);
            unsigned long long c23  = pk2(cur[2], cur[3]);
            unsigned long long c01b = 0ull;   // packed {0.f, 0.f}
            unsigned long long c23b = 0ull;

            // input channel rows (warp-uniform predicates)
            #pragma unroll
            for (int f = 0; f < 4; f++) {
                if (es[f]) {
                    ulonglong2 w = srec[rowe[f] + lane];
                    c01 = addx2(c01, w.x);
                    c23 = addx2(c23, w.y);
                }
            }
            // recurrent rows over z_prev (bits warp-uniform via ballot):
            //  1) adjacent both-spike pairs -> ONE precomputed both-row each
            //  2) remaining singles -> R4's 2-unrolled single-row loop
            #pragma unroll
            for (int k = 0; k < 4; k++) {
                unsigned bits = zb[k];
                unsigned both = bits & (bits >> 1) & 0x55555555u;
                unsigned rem  = bits & ~(both | (both << 1));

                const ulonglong2* bothp = srec + (HID + 16 * k) * 32 + lane;
                while (both) {
                    int p = __ffs(both) - 1; both &= both - 1;   // p = 2i
                    ulonglong2 w = bothp[(p >> 1) * 32];
                    c01b = addx2(c01b, w.x);
                    c23b = addx2(c23b, w.y);
                }

                const ulonglong2* rowp = srec + (32 * k) * 32 + lane;
                while (rem) {
                    int j1 = __ffs(rem) - 1; rem &= rem - 1;
                    ulonglong2 w1 = rowp[j1 * 32];
                    if (rem) {
                        int j2 = __ffs(rem) - 1; rem &= rem - 1;
                        ulonglong2 w2 = rowp[j2 * 32];
                        c01b = addx2(c01b, w2.x);
                        c23b = addx2(c23b, w2.y);
                    }
                    c01 = addx2(c01, w1.x);
                    c23 = addx2(c23, w1.y);
                }
            }
            c01 = addx2(c01, c01b);
            c23 = addx2(c23, c23b);
            upk2(c01, cur[0], cur[1]);
            upk2(c23, cur[2], cur[3]);

            // ---- publish new spikes ----
            #pragma unroll
            for (int k = 0; k < 4; k++)
                zb[k] = __ballot_sync(0xffffffffu, zn[k]);

            // ---- readout drive: (z_new * mask) @ w_out.T ----
            float d0 = 0.f, d1 = 0.f;
            #pragma unroll
            for (int k = 0; k < 4; k++) {
                float mv = zn[k] ? pm[k] : 0.0f;
                d0 = fmaf(mv, wo0[k], d0);
                d1 = fmaf(mv, wo1[k], d1);
            }
            unsigned long long d01 = pk2(d0, d1);
            #pragma unroll
            for (int off = 16; off; off >>= 1)
                d01 = addx2(d01, __shfl_xor_sync(0xffffffffu, d01, off));
            upk2(d01, d0, d1);

            // ---- LI readout (vo uses OLD io, matching reference) ----
            vo0 = fmaf(0.1f, io0 - vo0, vo0);
            vo1 = fmaf(0.1f, io1 - vo1, vo1);
            io0 = fmaf(0.8f, io0, d0);
            io1 = fmaf(0.8f, io1, d1);
            m0 = fmaxf(m0, vo0);
            m1 = fmaxf(m1, vo1);

            #pragma unroll
            for (int k = 0; k < 4; k++) pm[k] = pn[k];
            mrow = nrow;
        }

        if (lane == 0) {
            float mm = fmaxf(m0, m1);
            float e0 = expf(m0 - mm);
            float e1 = expf(m1 - mm);
            float inv = 1.0f / (e0 + e1);
            out[(size_t)b * 2 + 0] = e0 * inv;
            out[(size_t)b * 2 + 1] = e1 * inv;
        }
    }
}

extern "C" void kernel_launch(void* const* d_in, const int* in_sizes, int n_in,
                              void* d_out, int out_size) {
    const float* x     = (const float*)d_in[0];  // (B, 4)
    const float* w_in  = (const float*)d_in[1];  // (128, 8)
    const float* w_rec = (const float*)d_in[2];  // (128, 128)
    const float* w_out = (const float*)d_in[3];  // (2, 128)
    const float* mask  = (const float*)d_in[4];  // (40, B, 128)
    float* out = (float*)d_out;

    const int B = in_sizes[0] / 4;

    cudaFuncSetAttribute(snn_kernel,
                         cudaFuncAttributeMaxDynamicSharedMemorySize,
                         ROWS * HID * (int)sizeof(float));

    prep_kernel<<<(ROWS * HID + 255) / 256, 256>>>(w_rec, w_in);

    snn_kernel<<<NCTA, TPB, ROWS * HID * sizeof(float)>>>(
        x, w_out, mask, out, B);
}

// round 15
// speedup vs baseline: 1.0202x; 1.0106x over previous
#include <cuda_runtime.h>
#include <math.h>

#define SEQ 40
#define HID 128
#define WARPS 9
#define TPB (WARPS * 32)      // 288 x 3 CTAs -> 27 warps/SM (best measured config)
#define NCTA 444              // 148 SMs x 3 CTAs
#define ROWS (HID + 8)        // 128 w_rec rows + 8 w_in channel rows

// Lane-permuted weight tile:
//  row j (<128):   g_wT[j*128 + 4*lane + k] = w_rec[(32*k+lane)*128 + j]
//  row 128+ch:     g_wT[(128+ch)*128 + 4*lane + k] = w_in[(32*k+lane)*8 + ch]
__device__ float g_wT[ROWS * HID];
__device__ int g_ctr;

__global__ void prep_kernel(const float* __restrict__ w_rec,
                            const float* __restrict__ w_in) {
    int tid = blockIdx.x * blockDim.x + threadIdx.x;
    if (tid == 0) g_ctr = 0;
    if (tid < HID * HID) {
        int h = tid >> 7, j = tid & 127;
        g_wT[j * HID + ((h & 31) << 2) + (h >> 5)] = w_rec[tid];
    } else if (tid < HID * HID + HID * 8) {
        int r = tid - HID * HID;
        int h = r >> 3, ch = r & 7;
        g_wT[(HID + ch) * HID + ((h & 31) << 2) + (h >> 5)] = w_in[r];
    }
}

// ---- packed f32x2 helpers (sm_103a) ----
__device__ __forceinline__ unsigned long long pk2(float a, float b) {
    unsigned long long r;
    asm("mov.b64 %0, {%1, %2};" : "=l"(r) : "f"(a), "f"(b));
    return r;
}
__device__ __forceinline__ void upk2(unsigned long long v, float& a, float& b) {
    asm("mov.b64 {%0, %1}, %2;" : "=f"(a), "=f"(b) : "l"(v));
}
__device__ __forceinline__ unsigned long long addx2(unsigned long long a,
                                                    unsigned long long b) {
    unsigned long long r;
    asm("add.rn.f32x2 %0, %1, %2;" : "=l"(r) : "l"(a), "l"(b));
    return r;
}

__global__ __launch_bounds__(TPB, 3) void snn_kernel(
    const float* __restrict__ x,       // (B, 4)
    const float* __restrict__ w_out,   // (2, 128)
    const float* __restrict__ mask,    // (40, B, 128)
    float* __restrict__ out,           // (B, 2)
    int B)
{
    extern __shared__ ulonglong2 srec[];   // [ROWS][32 lanes] 16B = 68 KB

    {   // stage weights once per (persistent) CTA: coalesced, conflict-free
        const ulonglong2* src = reinterpret_cast<const ulonglong2*>(g_wT);
        for (int i = threadIdx.x; i < ROWS * 32; i += TPB)
            srec[i] = src[i];
    }
    __syncthreads();

    const int lane = threadIdx.x & 31;
    const size_t mstride = (size_t)B * HID;

    // lane-dependent readout weights: hoisted out of the work loop
    float wo0[4], wo1[4];
    #pragma unroll
    for (int k = 0; k < 4; k++) {
        int h = 32 * k + lane;
        wo0[k] = w_out[h];
        wo1[k] = w_out[HID + h];
    }

    for (;;) {
        // ---- per-warp work stealing: one batch element per grab ----
        int b;
        if (lane == 0) b = atomicAdd(&g_ctr, 1);
        b = __shfl_sync(0xffffffffu, b, 0);
        if (b >= B) break;

        // ---- encoder constants (warp-uniform) ----
        float c_in[4], venc[4];
        int rowe[4];     // srec element index of this feature's w_in row
        #pragma unroll
        for (int f = 0; f < 4; f++) {
            float xv = x[(size_t)b * 4 + f];
            int ch = (xv > 0.0f) ? f : (f + 4);
            rowe[f] = (HID + ch) * 32;
            c_in[f] = 50.0f * fabsf(xv);
            venc[f] = 0.0f;
        }

        // ---- state: lane owns hidden neurons h = 32k + lane ----
        float v[4]   = {0.f, 0.f, 0.f, 0.f};
        float cur[4] = {0.f, 0.f, 0.f, 0.f};
        float vo0 = 0.f, io0 = 0.f, vo1 = 0.f, io1 = 0.f;
        float m0 = -1e30f, m1 = -1e30f;
        unsigned zb[4] = {0u, 0u, 0u, 0u};

        const float* mrow = mask + (size_t)b * HID + lane;
        float pm[4];
        #pragma unroll
        for (int k = 0; k < 4; k++) pm[k] = __ldcs(mrow + 32 * k);

        #pragma unroll 2
        for (int t = 0; t < SEQ; t++) {
            // ---- prefetch next step's mask row ----
            const float* nrow = (t < SEQ - 1) ? (mrow + mstride) : mrow;
            float pn[4];
            #pragma unroll
            for (int k = 0; k < 4; k++) pn[k] = __ldcs(nrow + 32 * k);

            // ---- encoder LIF step (warp-uniform spikes) ----
            bool es[4];
            #pragma unroll
            for (int f = 0; f < 4; f++) {
                float vd = fmaf(0.1f, c_in[f] - venc[f], venc[f]);
                es[f] = vd > 1.0f;
                venc[f] = es[f] ? 0.0f : vd;
            }

            // ---- recurrent LIF membrane update ----
            bool zn[4];
            #pragma unroll
            for (int k = 0; k < 4; k++) {
                float vd = fmaf(0.1f, cur[k] - v[k], v[k]);
                zn[k] = vd > 1.0f;
                v[k] = zn[k] ? 0.0f : vd;
                cur[k] *= 0.8f;
            }

            // ---- sparse current accumulation, dual packed accumulators ----
            unsigned long long c01  = pk2(cur[0], cur[1]);
            unsigned long long c23  = pk2(cur[2], cur[3]);
            unsigned long long c01b = 0ull;   // packed {0.f, 0.f}
            unsigned long long c23b = 0ull;

            // input channel rows (warp-uniform predicates)
            #pragma unroll
            for (int f = 0; f < 4; f++) {
                if (es[f]) {
                    ulonglong2 w = srec[rowe[f] + lane];
                    c01 = addx2(c01, w.x);
                    c23 = addx2(c23, w.y);
                }
            }
            // recurrent rows over z_prev; bits warp-uniform (ballot), so the
            // control flow is non-divergent. Unroll-by-2: both LDS.128 issue
            // before their dependent adds (2x MLP in the hot loop).
            #pragma unroll
            for (int k = 0; k < 4; k++) {
                unsigned bits = zb[k];
                const ulonglong2* rowp = srec + (32 * k) * 32 + lane;
                while (bits) {
                    int j1 = __ffs(bits) - 1; bits &= bits - 1;
                    ulonglong2 w1 = rowp[j1 * 32];
                    if (bits) {
                        int j2 = __ffs(bits) - 1; bits &= bits - 1;
                        ulonglong2 w2 = rowp[j2 * 32];
                        c01b = addx2(c01b, w2.x);
                        c23b = addx2(c23b, w2.y);
                    }
                    c01 = addx2(c01, w1.x);
                    c23 = addx2(c23, w1.y);
                }
            }
            c01 = addx2(c01, c01b);
            c23 = addx2(c23, c23b);
            upk2(c01, cur[0], cur[1]);
            upk2(c23, cur[2], cur[3]);

            // ---- publish new spikes ----
            #pragma unroll
            for (int k = 0; k < 4; k++)
                zb[k] = __ballot_sync(0xffffffffu, zn[k]);

            // ---- readout drive: (z_new * mask) @ w_out.T ----
            float d0 = 0.f, d1 = 0.f;
            #pragma unroll
            for (int k = 0; k < 4; k++) {
                float mv = zn[k] ? pm[k] : 0.0f;
                d0 = fmaf(mv, wo0[k], d0);
                d1 = fmaf(mv, wo1[k], d1);
            }
            unsigned long long d01 = pk2(d0, d1);
            #pragma unroll
            for (int off = 16; off; off >>= 1)
                d01 = addx2(d01, __shfl_xor_sync(0xffffffffu, d01, off));
            upk2(d01, d0, d1);

            // ---- LI readout (vo uses OLD io, matching reference) ----
            vo0 = fmaf(0.1f, io0 - vo0, vo0);
            vo1 = fmaf(0.1f, io1 - vo1, vo1);
            io0 = fmaf(0.8f, io0, d0);
            io1 = fmaf(0.8f, io1, d1);
            m0 = fmaxf(m0, vo0);
            m1 = fmaxf(m1, vo1);

            #pragma unroll
            for (int k = 0; k < 4; k++) pm[k] = pn[k];
            mrow = nrow;
        }

        if (lane == 0) {
            float mm = fmaxf(m0, m1);
            float e0 = expf(m0 - mm);
            float e1 = expf(m1 - mm);
            float inv = 1.0f / (e0 + e1);
            out[(size_t)b * 2 + 0] = e0 * inv;
            out[(size_t)b * 2 + 1] = e1 * inv;
        }
    }
}

extern "C" void kernel_launch(void* const* d_in, const int* in_sizes, int n_in,
                              void* d_out, int out_size) {
    const float* x     = (const float*)d_in[0];  // (B, 4)
    const float* w_in  = (const float*)d_in[1];  // (128, 8)
    const float* w_rec = (const float*)d_in[2];  // (128, 128)
    const float* w_out = (const float*)d_in[3];  // (2, 128)
    const float* mask  = (const float*)d_in[4];  // (40, B, 128)
    float* out = (float*)d_out;

    const int B = in_sizes[0] / 4;

    cudaFuncSetAttribute(snn_kernel,
                         cudaFuncAttributeMaxDynamicSharedMemorySize,
                         ROWS * HID * (int)sizeof(float));

    prep_kernel<<<(HID * HID + HID * 8 + 255) / 256, 256>>>(w_rec, w_in);

    snn_kernel<<<NCTA, TPB, ROWS * HID * sizeof(float)>>>(
        x, w_out, mask, out, B);
}